// round 14
// baseline (speedup 1.0000x reference)
#include <cuda_runtime.h>
#include <cuda_bf16.h>
#include <math.h>

// ---------------- problem constants ----------------
#define B_    512
#define A_    8
#define NN    42
#define NIN   32
#define H     128
#define BFN   3
#define NH    4
#define LL    2
#define FF    256
#define OUTD  128
#define EE    41
#define HD    32
#define FB    (B_*A_)        // 4096
#define TT    (FB*NN)        // 172032

// ---------------- scratch (no allocs allowed) ----------------
__device__ float g_x[(size_t)TT*H];
__device__ float g_pos[(size_t)TT*H];
__device__ float g_qkv[(size_t)TT*3*H];
__device__ float g_fin[(size_t)FB*OUTD];
// tf32-rounded weights: W_in | qkv | aow | f1 | f2 | Wout
#define WOFF_WIN   0
#define WOFF_QKV   4096
#define WOFF_AOW   102400
#define WOFF_F1    135168
#define WOFF_F2    200704
#define WOFF_WOUT  266240
#define WTOTAL     954368
__device__ float g_w[WTOTAL];

// ---------------- helpers ----------------
__device__ __forceinline__ unsigned f2tf(float f)
{
    unsigned u;
    asm("cvt.rna.tf32.f32 %0, %1;" : "=r"(u) : "f"(f));
    return u;
}
__device__ __forceinline__ float f2tff(float f) { return __uint_as_float(f2tf(f)); }

__device__ __forceinline__ void mma_tf32(float* d, const unsigned* a, const unsigned* b)
{
    asm volatile("mma.sync.aligned.m16n8k8.row.col.f32.tf32.tf32.f32 "
                 "{%0,%1,%2,%3}, {%4,%5,%6,%7}, {%8,%9}, {%0,%1,%2,%3};\n"
                 : "+f"(d[0]), "+f"(d[1]), "+f"(d[2]), "+f"(d[3])
                 : "r"(a[0]), "r"(a[1]), "r"(a[2]), "r"(a[3]),
                   "r"(b[0]), "r"(b[1]));
}

__device__ __forceinline__ void cpa16(unsigned saddr, const void* g)
{
    asm volatile("cp.async.ca.shared.global [%0], [%1], 16;\n"
                 :: "r"(saddr), "l"(g));
}
#define CPA_COMMIT() asm volatile("cp.async.commit_group;\n" ::)
#define CPA_WAIT1()  asm volatile("cp.async.wait_group 1;\n" ::)
#define CPA_WAIT0()  asm volatile("cp.async.wait_group 0;\n" ::)

// ---------------- weight tf32 pre-round ----------------
__global__ __launch_bounds__(256) void wcvt_k(const float* __restrict__ src,
                                              float* __restrict__ dst, int n)
{
    int i = blockIdx.x * 256 + threadIdx.x;
    if (i < n) dst[i] = f2tff(src[i]);
}

// ---------------- positional encoding (single topological pass) ----------------
__global__ __launch_bounds__(128) void pos_kernel(const int* __restrict__ adj,
                                                  const int* __restrict__ order,
                                                  float* __restrict__ pos)
{
    int fb = blockIdx.x;
    int h  = threadIdx.x;
    __shared__ int   par[EE];
    __shared__ int   eidx[EE];
    __shared__ int   dep[NN];
    __shared__ float ps[NN][H];

    if (h < EE) {
        const int* e = &adj[((size_t)fb*EE + h)*3];
        par[h] = e[0] - fb*NN;
        int s = e[2] + 1; s = min(max(s, 0), BFN-1);
        eidx[h] = s;
    }
    __syncthreads();
    if (h == 0) {
        dep[0] = 0;
        for (int e = 0; e < EE; e++) {
            int p  = par[e];
            int dp = dep[p];
            dep[e + 1] = dp + 1;
            eidx[e] = dp * BFN + eidx[e];
        }
    }
    ps[0][h] = 0.f;
    __syncthreads();

#pragma unroll 1
    for (int e = 0; e < EE; e++) {
        float v = ps[par[e]][h] + ((h == eidx[e]) ? 1.f : 0.f);
        ps[e + 1][h] = v;
    }
    for (int n = 0; n < NN; n++)
        pos[((size_t)(fb*NN + n))*H + h] = ps[n][h];
}

// ---------------- TF32 GEMM, cp.async 3-stage  C = A[M,K] @ W[N,K]^T ----------
// Inputs assumed already tf32-rounded (producer-side); raw bits fed to mma.
#define BM  128
#define BN  128
#define BK  16
#define LDK 20
#define ASTG (BM*LDK)                 // words per stage (A or B): 2560
#define GEMM_SMEM_BYTES (3*2*ASTG*4)  // 61440

#define EPI_BIAS   0
#define EPI_RELU   1
#define EPI_ADD    2
#define EPI_ATOMIC 3
#define EPI_LN     4

template<int EPI>
__global__ __launch_bounds__(256)
void gemm_tc(const float* __restrict__ Ag, const float* __restrict__ Wg,
             const float* __restrict__ bias, const float* __restrict__ resid,
             const float* __restrict__ gam,  const float* __restrict__ bet,
             float* __restrict__ Cg, int M, int N, int K)
{
    extern __shared__ unsigned dsm[];
    unsigned* Asm = dsm;            // [3][BM][LDK]
    unsigned* Bsm = dsm + 3*ASTG;   // [3][BN][LDK]

    int m0 = blockIdx.x * BM;
    int n0 = blockIdx.y * BN;
    int per = K / gridDim.z;
    int ks  = blockIdx.z * per;
    int T   = per / BK;

    int tid  = threadIdx.x;
    int lane = tid & 31;
    int warp = tid >> 5;
    int wm = warp >> 2;
    int wn = warp & 3;
    int gid = lane >> 2;
    int tg  = lane & 3;
    int lrow = tid >> 1;
    int lcol = (tid & 1) * 8;

    float acc[4][4][4];
#pragma unroll
    for (int i = 0; i < 4; i++)
#pragma unroll
        for (int j = 0; j < 4; j++)
#pragma unroll
            for (int k = 0; k < 4; k++) acc[i][j][k] = 0.f;

    const float* Ap = Ag + (size_t)(m0 + lrow) * K + ks + lcol;
    const float* Wp = Wg + (size_t)(n0 + lrow) * K + ks + lcol;
    unsigned sa = (unsigned)__cvta_generic_to_shared(Asm) + (lrow*LDK + lcol)*4;
    unsigned sb = (unsigned)__cvta_generic_to_shared(Bsm) + (lrow*LDK + lcol)*4;

    // prologue: issue tiles 0,1
#pragma unroll
    for (int s = 0; s < 2; s++) {
        if (s < T) {
            cpa16(sa + s*ASTG*4,      Ap + s*BK);
            cpa16(sa + s*ASTG*4 + 16, Ap + s*BK + 4);
            cpa16(sb + s*ASTG*4,      Wp + s*BK);
            cpa16(sb + s*ASTG*4 + 16, Wp + s*BK + 4);
        }
        CPA_COMMIT();
    }

    for (int i = 0; i < T; i++) {
        CPA_WAIT1();
        __syncthreads();
        int nx = i + 2;
        if (nx < T) {
            int s = nx % 3;
            cpa16(sa + s*ASTG*4,      Ap + nx*BK);
            cpa16(sa + s*ASTG*4 + 16, Ap + nx*BK + 4);
            cpa16(sb + s*ASTG*4,      Wp + nx*BK);
            cpa16(sb + s*ASTG*4 + 16, Wp + nx*BK + 4);
        }
        CPA_COMMIT();

        const unsigned* Ac = Asm + (i % 3) * ASTG;
        const unsigned* Bc = Bsm + (i % 3) * ASTG;
#pragma unroll
        for (int k2 = 0; k2 < 2; k2++) {
            int kk = k2 * 8;
            unsigned af[4][4], bf[4][2];
#pragma unroll
            for (int mt = 0; mt < 4; mt++) {
                int r = wm*64 + mt*16 + gid;
                af[mt][0] = Ac[ r     *LDK + kk + tg];
                af[mt][1] = Ac[(r + 8)*LDK + kk + tg];
                af[mt][2] = Ac[ r     *LDK + kk + tg + 4];
                af[mt][3] = Ac[(r + 8)*LDK + kk + tg + 4];
            }
#pragma unroll
            for (int nt = 0; nt < 4; nt++) {
                int c = wn*32 + nt*8 + gid;
                bf[nt][0] = Bc[c*LDK + kk + tg];
                bf[nt][1] = Bc[c*LDK + kk + tg + 4];
            }
#pragma unroll
            for (int mt = 0; mt < 4; mt++)
#pragma unroll
                for (int nt = 0; nt < 4; nt++)
                    mma_tf32(acc[mt][nt], af[mt], bf[nt]);
        }
    }

    if constexpr (EPI == EPI_LN) {
        CPA_WAIT0();
        __syncthreads();
        float* red1 = (float*)dsm;           // [BM][4]
        float* red2 = red1 + BM*4;           // [BM][4]
        float mu0[4], mu1[4];

#pragma unroll
        for (int mt = 0; mt < 4; mt++) {
            int r = m0 + wm*64 + mt*16 + gid;
            float s0 = 0.f, s1 = 0.f;
#pragma unroll
            for (int nt = 0; nt < 4; nt++) {
                int c = wn*32 + nt*8 + 2*tg;
                float b0 = bias[c], b1 = bias[c + 1];
                float2 rl = *(const float2*)&resid[(size_t)r*128 + c];
                float2 rh = *(const float2*)&resid[(size_t)(r+8)*128 + c];
                acc[mt][nt][0] += b0 + rl.x;
                acc[mt][nt][1] += b1 + rl.y;
                acc[mt][nt][2] += b0 + rh.x;
                acc[mt][nt][3] += b1 + rh.y;
                s0 += acc[mt][nt][0] + acc[mt][nt][1];
                s1 += acc[mt][nt][2] + acc[mt][nt][3];
            }
            s0 += __shfl_xor_sync(0xffffffffu, s0, 1);
            s0 += __shfl_xor_sync(0xffffffffu, s0, 2);
            s1 += __shfl_xor_sync(0xffffffffu, s1, 1);
            s1 += __shfl_xor_sync(0xffffffffu, s1, 2);
            if (tg == 0) {
                red1[(wm*64 + mt*16 + gid    )*4 + wn] = s0;
                red1[(wm*64 + mt*16 + gid + 8)*4 + wn] = s1;
            }
        }
        __syncthreads();
#pragma unroll
        for (int mt = 0; mt < 4; mt++) {
            int rl_ = wm*64 + mt*16 + gid;
            mu0[mt] = (red1[rl_*4+0] + red1[rl_*4+1] + red1[rl_*4+2] + red1[rl_*4+3]) * (1.f/128.f);
            mu1[mt] = (red1[(rl_+8)*4+0] + red1[(rl_+8)*4+1] + red1[(rl_+8)*4+2] + red1[(rl_+8)*4+3]) * (1.f/128.f);
            float q0 = 0.f, q1 = 0.f;
#pragma unroll
            for (int nt = 0; nt < 4; nt++) {
                float d0 = acc[mt][nt][0] - mu0[mt];
                float d1 = acc[mt][nt][1] - mu0[mt];
                float d2 = acc[mt][nt][2] - mu1[mt];
                float d3 = acc[mt][nt][3] - mu1[mt];
                q0 += d0*d0 + d1*d1;
                q1 += d2*d2 + d3*d3;
            }
            q0 += __shfl_xor_sync(0xffffffffu, q0, 1);
            q0 += __shfl_xor_sync(0xffffffffu, q0, 2);
            q1 += __shfl_xor_sync(0xffffffffu, q1, 1);
            q1 += __shfl_xor_sync(0xffffffffu, q1, 2);
            if (tg == 0) {
                red2[rl_*4 + wn]     = q0;
                red2[(rl_+8)*4 + wn] = q1;
            }
        }
        __syncthreads();
#pragma unroll
        for (int mt = 0; mt < 4; mt++) {
            int rl_ = wm*64 + mt*16 + gid;
            int r = m0 + rl_;
            float rs0 = rsqrtf((red2[rl_*4+0] + red2[rl_*4+1] + red2[rl_*4+2] + red2[rl_*4+3]) * (1.f/128.f) + 1e-5f);
            float rs1 = rsqrtf((red2[(rl_+8)*4+0] + red2[(rl_+8)*4+1] + red2[(rl_+8)*4+2] + red2[(rl_+8)*4+3]) * (1.f/128.f) + 1e-5f);
#pragma unroll
            for (int nt = 0; nt < 4; nt++) {
                int c = wn*32 + nt*8 + 2*tg;
                float g0 = gam[c], g1 = gam[c + 1];
                float e0 = bet[c], e1 = bet[c + 1];
                float v0 = f2tff((acc[mt][nt][0] - mu0[mt]) * rs0 * g0 + e0);
                float v1 = f2tff((acc[mt][nt][1] - mu0[mt]) * rs0 * g1 + e1);
                float v2 = f2tff((acc[mt][nt][2] - mu1[mt]) * rs1 * g0 + e0);
                float v3 = f2tff((acc[mt][nt][3] - mu1[mt]) * rs1 * g1 + e1);
                *(float2*)&Cg[(size_t)r*128 + c]     = make_float2(v0, v1);
                *(float2*)&Cg[(size_t)(r+8)*128 + c] = make_float2(v2, v3);
            }
        }
    } else {
#pragma unroll
        for (int mt = 0; mt < 4; mt++) {
#pragma unroll
            for (int nt = 0; nt < 4; nt++) {
                int r = m0 + wm*64 + mt*16 + gid;
                int c = n0 + wn*32 + nt*8 + 2*tg;
                if constexpr (EPI == EPI_ATOMIC) {
                    atomicAdd(&Cg[(size_t)r*N + c],         acc[mt][nt][0]);
                    atomicAdd(&Cg[(size_t)r*N + c + 1],     acc[mt][nt][1]);
                    atomicAdd(&Cg[(size_t)(r+8)*N + c],     acc[mt][nt][2]);
                    atomicAdd(&Cg[(size_t)(r+8)*N + c + 1], acc[mt][nt][3]);
                } else {
                    float b0 = bias[c], b1 = bias[c + 1];
                    float v0 = acc[mt][nt][0] + b0, v1 = acc[mt][nt][1] + b1;
                    float v2 = acc[mt][nt][2] + b0, v3 = acc[mt][nt][3] + b1;
                    if constexpr (EPI == EPI_RELU) {
                        v0 = fmaxf(v0, 0.f); v1 = fmaxf(v1, 0.f);
                        v2 = fmaxf(v2, 0.f); v3 = fmaxf(v3, 0.f);
                    }
                    if constexpr (EPI == EPI_ADD) {
                        float2 rl = *(const float2*)&resid[(size_t)r*N + c];
                        float2 rh = *(const float2*)&resid[(size_t)(r+8)*N + c];
                        v0 += rl.x; v1 += rl.y; v2 += rh.x; v3 += rh.y;
                    }
                    v0 = f2tff(v0); v1 = f2tff(v1); v2 = f2tff(v2); v3 = f2tff(v3);
                    *(float2*)&Cg[(size_t)r*N + c]     = make_float2(v0, v1);
                    *(float2*)&Cg[(size_t)(r+8)*N + c] = make_float2(v2, v3);
                }
            }
        }
    }
}

// ---------------- tensor-core attention -------------------------------------
// One block per forest (256 thr). warp -> (head = warp>>1, m-half = warp&1).
// Inputs already tf32-rounded by qkv epilogue; raw bits fed to mma.
#define NP   48
#define QSS  132
#define PSS  52
#define ATTN_SMEM_WORDS (2*NP*QSS + H*PSS)
#define ATTN_SMEM_BYTES (ATTN_SMEM_WORDS*4)

__global__ __launch_bounds__(256, 2) void attn_k(const float* __restrict__ qkv,
                                                 float* __restrict__ o)
{
    extern __shared__ unsigned sm[];
    unsigned* qs = sm;
    unsigned* ks = sm + NP*QSS;
    unsigned* ps = sm;                 // overlay after QK phase
    unsigned* vt = sm + 2*NP*QSS;

    int fb  = blockIdx.x;
    int tid = threadIdx.x;
    size_t base = (size_t)fb * NN * (3*H);

    for (int idx = tid; idx < NP*H; idx += 256) {
        int n = idx >> 7, c = idx & 127;
        unsigned qv = 0, kv = 0, vv = 0;
        if (n < NN) {
            const unsigned* row = (const unsigned*)&qkv[base + (size_t)n*(3*H)];
            qv = row[c];
            kv = row[H + c];
            vv = row[2*H + c];
        }
        qs[n*QSS + c] = qv;
        ks[n*QSS + c] = kv;
        vt[c*PSS + n] = vv;
    }
    __syncthreads();

    int warp = tid >> 5, lane = tid & 31;
    int gid = lane >> 2, tg = lane & 3;
    int h     = warp >> 1;
    int grp   = warp & 1;
    int hc    = h * HD;
    int mb    = grp ? 32 : 0;
    int mstep = grp ? 0 : 16;

    // ---- S = Q @ K^T ----
    float acc[2][6][4];
#pragma unroll
    for (int a = 0; a < 2; a++)
#pragma unroll
        for (int b = 0; b < 6; b++)
#pragma unroll
            for (int c = 0; c < 4; c++) acc[a][b][c] = 0.f;

#pragma unroll
    for (int k = 0; k < 4; k++) {
        int kk = hc + k*8;
        unsigned af[2][4], bf[6][2];
#pragma unroll
        for (int mt = 0; mt < 2; mt++) {
            int r = mb + mt*mstep + gid;
            af[mt][0] = qs[r*QSS + kk + tg];
            af[mt][1] = qs[(r+8)*QSS + kk + tg];
            af[mt][2] = qs[r*QSS + kk + tg + 4];
            af[mt][3] = qs[(r+8)*QSS + kk + tg + 4];
        }
#pragma unroll
        for (int nt = 0; nt < 6; nt++) {
            int n = nt*8 + gid;
            bf[nt][0] = ks[n*QSS + kk + tg];
            bf[nt][1] = ks[n*QSS + kk + tg + 4];
        }
#pragma unroll
        for (int mt = 0; mt < 2; mt++)
#pragma unroll
            for (int nt = 0; nt < 6; nt++)
                mma_tf32(acc[mt][nt], af[mt], bf[nt]);
    }
    __syncthreads();

    // ---- softmax + store P (tf32) ----
    const float scale = 0.17677669529663687f;
    unsigned* psh = ps + h*(NP*PSS);
#pragma unroll
    for (int mt = 0; mt < 2; mt++) {
        int r0 = mb + mt*mstep + gid;
        float m0 = -1e30f, m1 = -1e30f;
#pragma unroll
        for (int nt = 0; nt < 6; nt++) {
            int c0 = nt*8 + 2*tg;
            float v0 = (c0     < NN) ? acc[mt][nt][0]*scale : -1e30f;
            float v1 = (c0 + 1 < NN) ? acc[mt][nt][1]*scale : -1e30f;
            float v2 = (c0     < NN) ? acc[mt][nt][2]*scale : -1e30f;
            float v3 = (c0 + 1 < NN) ? acc[mt][nt][3]*scale : -1e30f;
            acc[mt][nt][0] = v0; acc[mt][nt][1] = v1;
            acc[mt][nt][2] = v2; acc[mt][nt][3] = v3;
            m0 = fmaxf(m0, fmaxf(v0, v1));
            m1 = fmaxf(m1, fmaxf(v2, v3));
        }
        m0 = fmaxf(m0, __shfl_xor_sync(0xffffffffu, m0, 1));
        m0 = fmaxf(m0, __shfl_xor_sync(0xffffffffu, m0, 2));
        m1 = fmaxf(m1, __shfl_xor_sync(0xffffffffu, m1, 1));
        m1 = fmaxf(m1, __shfl_xor_sync(0xffffffffu, m1, 2));
        float s0 = 0.f, s1 = 0.f;
#pragma unroll
        for (int nt = 0; nt < 6; nt++) {
            float p0 = __expf(acc[mt][nt][0] - m0);
            float p1 = __expf(acc[mt][nt][1] - m0);
            float p2 = __expf(acc[mt][nt][2] - m1);
            float p3 = __expf(acc[mt][nt][3] - m1);
            acc[mt][nt][0] = p0; acc[mt][nt][1] = p1;
            acc[mt][nt][2] = p2; acc[mt][nt][3] = p3;
            s0 += p0 + p1; s1 += p2 + p3;
        }
        s0 += __shfl_xor_sync(0xffffffffu, s0, 1);
        s0 += __shfl_xor_sync(0xffffffffu, s0, 2);
        s1 += __shfl_xor_sync(0xffffffffu, s1, 1);
        s1 += __shfl_xor_sync(0xffffffffu, s1, 2);
        float i0 = 1.f / s0, i1 = 1.f / s1;
#pragma unroll
        for (int nt = 0; nt < 6; nt++) {
            int c0 = nt*8 + 2*tg;
            psh[ r0     *PSS + c0    ] = f2tf(acc[mt][nt][0] * i0);
            psh[ r0     *PSS + c0 + 1] = f2tf(acc[mt][nt][1] * i0);
            psh[(r0 + 8)*PSS + c0    ] = f2tf(acc[mt][nt][2] * i1);
            psh[(r0 + 8)*PSS + c0 + 1] = f2tf(acc[mt][nt][3] * i1);
        }
    }
    __syncthreads();

    // ---- O = P @ V ----
    float oa[2][4][4];
#pragma unroll
    for (int a = 0; a < 2; a++)
#pragma unroll
        for (int b = 0; b < 4; b++)
#pragma unroll
            for (int c = 0; c < 4; c++) oa[a][b][c] = 0.f;

#pragma unroll
    for (int k = 0; k < 6; k++) {
        int kk = k*8;
        unsigned af[2][4], bf[4][2];
#pragma unroll
        for (int mt = 0; mt < 2; mt++) {
            int r = mb + mt*mstep + gid;
            af[mt][0] = psh[ r     *PSS + kk + tg];
            af[mt][1] = psh[(r + 8)*PSS + kk + tg];
            af[mt][2] = psh[ r     *PSS + kk + tg + 4];
            af[mt][3] = psh[(r + 8)*PSS + kk + tg + 4];
        }
#pragma unroll
        for (int nt = 0; nt < 4; nt++) {
            int n = hc + nt*8 + gid;
            bf[nt][0] = vt[n*PSS + kk + tg];
            bf[nt][1] = vt[n*PSS + kk + tg + 4];
        }
#pragma unroll
        for (int mt = 0; mt < 2; mt++)
#pragma unroll
            for (int nt = 0; nt < 4; nt++)
                mma_tf32(oa[mt][nt], af[mt], bf[nt]);
    }

#pragma unroll
    for (int mt = 0; mt < 2; mt++)
#pragma unroll
        for (int nt = 0; nt < 4; nt++) {
            int r = mb + mt*mstep + gid;
            int c = hc + nt*8 + 2*tg;
            if (r < NN)
                *(float2*)&o[((size_t)(fb*NN + r))*H + c] =
                    make_float2(f2tff(oa[mt][nt][0]), f2tff(oa[mt][nt][1]));
            if (r + 8 < NN)
                *(float2*)&o[((size_t)(fb*NN + r + 8))*H + c] =
                    make_float2(f2tff(oa[mt][nt][2]), f2tff(oa[mt][nt][3]));
        }
}

// ---------------- final LN over OUT=128 ----------------
__global__ __launch_bounds__(128) void lnf_k(const float* __restrict__ fin,
                                             const float* __restrict__ bo,
                                             const float* __restrict__ g,
                                             const float* __restrict__ b,
                                             float* __restrict__ out)
{
    int r = blockIdx.x, c = threadIdx.x;
    float v = fin[(size_t)r*OUTD + c] + bo[c];
    __shared__ float red[4];
    float s = v;
#pragma unroll
    for (int off = 16; off; off >>= 1) s += __shfl_xor_sync(0xffffffffu, s, off);
    if ((c & 31) == 0) red[c >> 5] = s;
    __syncthreads();
    float mu = (red[0] + red[1] + red[2] + red[3]) * (1.f/128.f);
    __syncthreads();
    float d = v - mu;
    float q = d * d;
#pragma unroll
    for (int off = 16; off; off >>= 1) q += __shfl_xor_sync(0xffffffffu, q, off);
    if ((c & 31) == 0) red[c >> 5] = q;
    __syncthreads();
    float var = (red[0] + red[1] + red[2] + red[3]) * (1.f/128.f);
    float rs = rsqrtf(var + 1e-5f);
    out[(size_t)r*OUTD + c] = d * rs * g[c] + b[c];
}

// ---------------- launch ----------------
extern "C" void kernel_launch(void* const* d_in, const int* in_sizes, int n_in,
                              void* d_out, int out_size)
{
    const float* forest = (const float*)d_in[0];
    const int*   adj    = (const int*)  d_in[1];
    const int*   order  = (const int*)  d_in[2];
    const float* W_in   = (const float*)d_in[3];
    const float* b_in   = (const float*)d_in[4];
    const float* qkv_w  = (const float*)d_in[5];
    const float* qkv_b  = (const float*)d_in[6];
    const float* aow    = (const float*)d_in[7];
    const float* aob    = (const float*)d_in[8];
    const float* f1w    = (const float*)d_in[9];
    const float* f1b    = (const float*)d_in[10];
    const float* f2w    = (const float*)d_in[11];
    const float* f2b    = (const float*)d_in[12];
    const float* ln1g   = (const float*)d_in[13];
    const float* ln1b   = (const float*)d_in[14];
    const float* ln2g   = (const float*)d_in[15];
    const float* ln2b   = (const float*)d_in[16];
    const float* Wout   = (const float*)d_in[17];
    const float* bout   = (const float*)d_in[18];
    const float* lnfg   = (const float*)d_in[19];
    const float* lnfb   = (const float*)d_in[20];

    float *px, *ppos, *pqkv, *pfin, *pw;
    cudaGetSymbolAddress((void**)&px,   g_x);
    cudaGetSymbolAddress((void**)&ppos, g_pos);
    cudaGetSymbolAddress((void**)&pqkv, g_qkv);
    cudaGetSymbolAddress((void**)&pfin, g_fin);
    cudaGetSymbolAddress((void**)&pw,   g_w);

    cudaFuncSetAttribute(attn_k, cudaFuncAttributeMaxDynamicSharedMemorySize,
                         ATTN_SMEM_BYTES);
    cudaFuncSetAttribute(gemm_tc<EPI_BIAS>,   cudaFuncAttributeMaxDynamicSharedMemorySize, GEMM_SMEM_BYTES);
    cudaFuncSetAttribute(gemm_tc<EPI_RELU>,   cudaFuncAttributeMaxDynamicSharedMemorySize, GEMM_SMEM_BYTES);
    cudaFuncSetAttribute(gemm_tc<EPI_ADD>,    cudaFuncAttributeMaxDynamicSharedMemorySize, GEMM_SMEM_BYTES);
    cudaFuncSetAttribute(gemm_tc<EPI_ATOMIC>, cudaFuncAttributeMaxDynamicSharedMemorySize, GEMM_SMEM_BYTES);
    cudaFuncSetAttribute(gemm_tc<EPI_LN>,     cudaFuncAttributeMaxDynamicSharedMemorySize, GEMM_SMEM_BYTES);

    // 0) pre-round weights to tf32
    wcvt_k<<<(4096   + 255)/256, 256>>>(W_in,  pw + WOFF_WIN,  4096);
    wcvt_k<<<(98304  + 255)/256, 256>>>(qkv_w, pw + WOFF_QKV,  98304);
    wcvt_k<<<(32768  + 255)/256, 256>>>(aow,   pw + WOFF_AOW,  32768);
    wcvt_k<<<(65536  + 255)/256, 256>>>(f1w,   pw + WOFF_F1,   65536);
    wcvt_k<<<(65536  + 255)/256, 256>>>(f2w,   pw + WOFF_F2,   65536);
    wcvt_k<<<(688128 + 255)/256, 256>>>(Wout,  pw + WOFF_WOUT, 688128);

    // 1) positional encoding
    pos_kernel<<<FB, 128>>>(adj, order, ppos);

    // 2) embed: x = forest @ W_in^T + b_in + pos  (tf32-rounded out)
    gemm_tc<EPI_ADD><<<dim3(TT/BM, 1, 1), 256, GEMM_SMEM_BYTES>>>(
        forest, pw + WOFF_WIN, b_in, ppos, nullptr, nullptr, px, TT, H, NIN);

    for (int l = 0; l < LL; l++) {
        gemm_tc<EPI_BIAS><<<dim3(TT/BM, 3, 1), 256, GEMM_SMEM_BYTES>>>(
            px, pw + WOFF_QKV + (size_t)l*3*H*H, qkv_b + (size_t)l*3*H,
            nullptr, nullptr, nullptr, pqkv, TT, 3*H, H);
        attn_k<<<FB, 256, ATTN_SMEM_BYTES>>>(pqkv, ppos);
        gemm_tc<EPI_LN><<<dim3(TT/BM, 1, 1), 256, GEMM_SMEM_BYTES>>>(
            ppos, pw + WOFF_AOW + (size_t)l*H*H, aob + (size_t)l*H, px,
            ln1g + (size_t)l*H, ln1b + (size_t)l*H, px, TT, H, H);
        gemm_tc<EPI_RELU><<<dim3(TT/BM, 2, 1), 256, GEMM_SMEM_BYTES>>>(
            px, pw + WOFF_F1 + (size_t)l*FF*H, f1b + (size_t)l*FF,
            nullptr, nullptr, nullptr, pqkv, TT, FF, H);
        gemm_tc<EPI_LN><<<dim3(TT/BM, 1, 1), 256, GEMM_SMEM_BYTES>>>(
            pqkv, pw + WOFF_F2 + (size_t)l*H*FF, f2b + (size_t)l*H, px,
            ln2g + (size_t)l*H, ln2b + (size_t)l*H, px, TT, H, FF);
    }

    // 3) final: out = LN( x.reshape(FB, NN*H) @ Wout^T + b_out )
    cudaMemsetAsync(pfin, 0, (size_t)FB*OUTD*sizeof(float));
    gemm_tc<EPI_ATOMIC><<<dim3(FB/BM, 1, 8), 256, GEMM_SMEM_BYTES>>>(
        px, pw + WOFF_WOUT, nullptr, nullptr, nullptr, nullptr, pfin, FB, OUTD, NN*H);
    lnf_k<<<FB, 128>>>(pfin, bout, lnfg, lnfb, (float*)d_out);
}

// round 16
// speedup vs baseline: 1.3023x; 1.3023x over previous
#include <cuda_runtime.h>
#include <cuda_bf16.h>
#include <math.h>

// ---------------- problem constants ----------------
#define B_    512
#define A_    8
#define NN    42
#define NIN   32
#define H     128
#define BFN   3
#define NH    4
#define LL    2
#define FF    256
#define OUTD  128
#define EE    41
#define HD    32
#define FB    (B_*A_)        // 4096
#define TT    (FB*NN)        // 172032

// ---------------- scratch (no allocs allowed) ----------------
__device__ float g_x[(size_t)TT*H];
__device__ float g_pos[(size_t)TT*H];
__device__ float g_qkv[(size_t)TT*3*H];
__device__ float g_fin[(size_t)FB*OUTD];

// ---------------- positional encoding (single topological pass) ----------------
__global__ __launch_bounds__(128) void pos_kernel(const int* __restrict__ adj,
                                                  const int* __restrict__ order,
                                                  float* __restrict__ pos)
{
    int fb = blockIdx.x;
    int h  = threadIdx.x;
    __shared__ int   par[EE];
    __shared__ int   eidx[EE];
    __shared__ int   dep[NN];
    __shared__ float ps[NN][H];

    if (h < EE) {
        const int* e = &adj[((size_t)fb*EE + h)*3];
        par[h] = e[0] - fb*NN;
        int s = e[2] + 1; s = min(max(s, 0), BFN-1);
        eidx[h] = s;
    }
    __syncthreads();
    if (h == 0) {
        dep[0] = 0;
        for (int e = 0; e < EE; e++) {
            int p  = par[e];
            int dp = dep[p];
            dep[e + 1] = dp + 1;
            eidx[e] = dp * BFN + eidx[e];
        }
    }
    ps[0][h] = 0.f;
    __syncthreads();

#pragma unroll 1
    for (int e = 0; e < EE; e++) {
        float v = ps[par[e]][h] + ((h == eidx[e]) ? 1.f : 0.f);
        ps[e + 1][h] = v;
    }
    for (int n = 0; n < NN; n++)
        pos[((size_t)(fb*NN + n))*H + h] = ps[n][h];
}

// ---------------- helpers ----------------
__device__ __forceinline__ unsigned f2tf(float f)
{
    unsigned u;
    asm("cvt.rna.tf32.f32 %0, %1;" : "=r"(u) : "f"(f));
    return u;
}

__device__ __forceinline__ void mma_tf32(float* d, const unsigned* a, const unsigned* b)
{
    asm volatile("mma.sync.aligned.m16n8k8.row.col.f32.tf32.tf32.f32 "
                 "{%0,%1,%2,%3}, {%4,%5,%6,%7}, {%8,%9}, {%0,%1,%2,%3};\n"
                 : "+f"(d[0]), "+f"(d[1]), "+f"(d[2]), "+f"(d[3])
                 : "r"(a[0]), "r"(a[1]), "r"(a[2]), "r"(a[3]),
                   "r"(b[0]), "r"(b[1]));
}

// ---------------- TF32 tensor-core GEMM  C = A[M,K] @ W[N,K]^T ----------------
// (R12 version: static 2-stage smem, register prefetch, cvt in loop)
#define BM  128
#define BN  128
#define BK  16
#define LDK 20

#define EPI_BIAS   0
#define EPI_RELU   1
#define EPI_ADD    2
#define EPI_ATOMIC 3
#define EPI_LN     4

template<int EPI>
__global__ __launch_bounds__(256)
void gemm_tc(const float* __restrict__ Ag, const float* __restrict__ Wg,
             const float* __restrict__ bias, const float* __restrict__ resid,
             const float* __restrict__ gam,  const float* __restrict__ bet,
             float* __restrict__ Cg, int M, int N, int K)
{
    __shared__ unsigned As[2][BM][LDK];
    __shared__ unsigned Bs[2][BN][LDK];

    int m0 = blockIdx.x * BM;
    int n0 = blockIdx.y * BN;
    int per = K / gridDim.z;
    int ks  = blockIdx.z * per;
    int ke  = ks + per;

    int tid  = threadIdx.x;
    int lane = tid & 31;
    int warp = tid >> 5;
    int wm = warp >> 2;
    int wn = warp & 3;
    int gid = lane >> 2;
    int tg  = lane & 3;
    int lrow = tid >> 1;
    int lcol = (tid & 1) * 8;

    float acc[4][4][4];
#pragma unroll
    for (int i = 0; i < 4; i++)
#pragma unroll
        for (int j = 0; j < 4; j++)
#pragma unroll
            for (int k = 0; k < 4; k++) acc[i][j][k] = 0.f;

    const float* Ap = Ag + (size_t)(m0 + lrow) * K + lcol;
    const float* Wp = Wg + (size_t)(n0 + lrow) * K + lcol;

    float4 av0, av1, wv0, wv1;

    av0 = *(const float4*)(Ap + ks);
    av1 = *(const float4*)(Ap + ks + 4);
    wv0 = *(const float4*)(Wp + ks);
    wv1 = *(const float4*)(Wp + ks + 4);
    *(uint4*)&As[0][lrow][lcol]     = make_uint4(f2tf(av0.x), f2tf(av0.y), f2tf(av0.z), f2tf(av0.w));
    *(uint4*)&As[0][lrow][lcol + 4] = make_uint4(f2tf(av1.x), f2tf(av1.y), f2tf(av1.z), f2tf(av1.w));
    *(uint4*)&Bs[0][lrow][lcol]     = make_uint4(f2tf(wv0.x), f2tf(wv0.y), f2tf(wv0.z), f2tf(wv0.w));
    *(uint4*)&Bs[0][lrow][lcol + 4] = make_uint4(f2tf(wv1.x), f2tf(wv1.y), f2tf(wv1.z), f2tf(wv1.w));
    __syncthreads();

    int cur = 0;
    for (int kt = ks; kt < ke; kt += BK) {
        bool more = (kt + BK) < ke;
        if (more) {
            av0 = *(const float4*)(Ap + kt + BK);
            av1 = *(const float4*)(Ap + kt + BK + 4);
            wv0 = *(const float4*)(Wp + kt + BK);
            wv1 = *(const float4*)(Wp + kt + BK + 4);
        }

#pragma unroll
        for (int k2 = 0; k2 < 2; k2++) {
            int kk = k2 * 8;
            unsigned af[4][4], bf[4][2];
#pragma unroll
            for (int mt = 0; mt < 4; mt++) {
                int r = wm*64 + mt*16 + gid;
                af[mt][0] = As[cur][r    ][kk + tg];
                af[mt][1] = As[cur][r + 8][kk + tg];
                af[mt][2] = As[cur][r    ][kk + tg + 4];
                af[mt][3] = As[cur][r + 8][kk + tg + 4];
            }
#pragma unroll
            for (int nt = 0; nt < 4; nt++) {
                int c = wn*32 + nt*8 + gid;
                bf[nt][0] = Bs[cur][c][kk + tg];
                bf[nt][1] = Bs[cur][c][kk + tg + 4];
            }
#pragma unroll
            for (int mt = 0; mt < 4; mt++)
#pragma unroll
                for (int nt = 0; nt < 4; nt++)
                    mma_tf32(acc[mt][nt], af[mt], bf[nt]);
        }

        if (more) {
            int nxt = cur ^ 1;
            *(uint4*)&As[nxt][lrow][lcol]     = make_uint4(f2tf(av0.x), f2tf(av0.y), f2tf(av0.z), f2tf(av0.w));
            *(uint4*)&As[nxt][lrow][lcol + 4] = make_uint4(f2tf(av1.x), f2tf(av1.y), f2tf(av1.z), f2tf(av1.w));
            *(uint4*)&Bs[nxt][lrow][lcol]     = make_uint4(f2tf(wv0.x), f2tf(wv0.y), f2tf(wv0.z), f2tf(wv0.w));
            *(uint4*)&Bs[nxt][lrow][lcol + 4] = make_uint4(f2tf(wv1.x), f2tf(wv1.y), f2tf(wv1.z), f2tf(wv1.w));
            __syncthreads();
        }
        cur ^= 1;
    }

    if constexpr (EPI == EPI_LN) {
        __shared__ float red1[BM][4];
        __shared__ float red2[BM][4];
        float mu0[4], mu1[4];

#pragma unroll
        for (int mt = 0; mt < 4; mt++) {
            int r = m0 + wm*64 + mt*16 + gid;
            float s0 = 0.f, s1 = 0.f;
#pragma unroll
            for (int nt = 0; nt < 4; nt++) {
                int c = wn*32 + nt*8 + 2*tg;
                float b0 = bias[c], b1 = bias[c + 1];
                float2 rl = *(const float2*)&resid[(size_t)r*128 + c];
                float2 rh = *(const float2*)&resid[(size_t)(r+8)*128 + c];
                acc[mt][nt][0] += b0 + rl.x;
                acc[mt][nt][1] += b1 + rl.y;
                acc[mt][nt][2] += b0 + rh.x;
                acc[mt][nt][3] += b1 + rh.y;
                s0 += acc[mt][nt][0] + acc[mt][nt][1];
                s1 += acc[mt][nt][2] + acc[mt][nt][3];
            }
            s0 += __shfl_xor_sync(0xffffffffu, s0, 1);
            s0 += __shfl_xor_sync(0xffffffffu, s0, 2);
            s1 += __shfl_xor_sync(0xffffffffu, s1, 1);
            s1 += __shfl_xor_sync(0xffffffffu, s1, 2);
            if (tg == 0) {
                red1[wm*64 + mt*16 + gid    ][wn] = s0;
                red1[wm*64 + mt*16 + gid + 8][wn] = s1;
            }
        }
        __syncthreads();
#pragma unroll
        for (int mt = 0; mt < 4; mt++) {
            int rl_ = wm*64 + mt*16 + gid;
            mu0[mt] = (red1[rl_    ][0] + red1[rl_    ][1] + red1[rl_    ][2] + red1[rl_    ][3]) * (1.f/128.f);
            mu1[mt] = (red1[rl_ + 8][0] + red1[rl_ + 8][1] + red1[rl_ + 8][2] + red1[rl_ + 8][3]) * (1.f/128.f);
            float q0 = 0.f, q1 = 0.f;
#pragma unroll
            for (int nt = 0; nt < 4; nt++) {
                float d0 = acc[mt][nt][0] - mu0[mt];
                float d1 = acc[mt][nt][1] - mu0[mt];
                float d2 = acc[mt][nt][2] - mu1[mt];
                float d3 = acc[mt][nt][3] - mu1[mt];
                q0 += d0*d0 + d1*d1;
                q1 += d2*d2 + d3*d3;
            }
            q0 += __shfl_xor_sync(0xffffffffu, q0, 1);
            q0 += __shfl_xor_sync(0xffffffffu, q0, 2);
            q1 += __shfl_xor_sync(0xffffffffu, q1, 1);
            q1 += __shfl_xor_sync(0xffffffffu, q1, 2);
            if (tg == 0) {
                red2[rl_    ][wn] = q0;
                red2[rl_ + 8][wn] = q1;
            }
        }
        __syncthreads();
#pragma unroll
        for (int mt = 0; mt < 4; mt++) {
            int rl_ = wm*64 + mt*16 + gid;
            int r = m0 + rl_;
            float rs0 = rsqrtf((red2[rl_    ][0] + red2[rl_    ][1] + red2[rl_    ][2] + red2[rl_    ][3]) * (1.f/128.f) + 1e-5f);
            float rs1 = rsqrtf((red2[rl_ + 8][0] + red2[rl_ + 8][1] + red2[rl_ + 8][2] + red2[rl_ + 8][3]) * (1.f/128.f) + 1e-5f);
#pragma unroll
            for (int nt = 0; nt < 4; nt++) {
                int c = wn*32 + nt*8 + 2*tg;
                float g0 = gam[c], g1 = gam[c + 1];
                float e0 = bet[c], e1 = bet[c + 1];
                float v0 = (acc[mt][nt][0] - mu0[mt]) * rs0 * g0 + e0;
                float v1 = (acc[mt][nt][1] - mu0[mt]) * rs0 * g1 + e1;
                float v2 = (acc[mt][nt][2] - mu1[mt]) * rs1 * g0 + e0;
                float v3 = (acc[mt][nt][3] - mu1[mt]) * rs1 * g1 + e1;
                *(float2*)&Cg[(size_t)r*128 + c]     = make_float2(v0, v1);
                *(float2*)&Cg[(size_t)(r+8)*128 + c] = make_float2(v2, v3);
            }
        }
    } else {
#pragma unroll
        for (int mt = 0; mt < 4; mt++) {
#pragma unroll
            for (int nt = 0; nt < 4; nt++) {
                int r = m0 + wm*64 + mt*16 + gid;
                int c = n0 + wn*32 + nt*8 + 2*tg;
                if constexpr (EPI == EPI_ATOMIC) {
                    atomicAdd(&Cg[(size_t)r*N + c],         acc[mt][nt][0]);
                    atomicAdd(&Cg[(size_t)r*N + c + 1],     acc[mt][nt][1]);
                    atomicAdd(&Cg[(size_t)(r+8)*N + c],     acc[mt][nt][2]);
                    atomicAdd(&Cg[(size_t)(r+8)*N + c + 1], acc[mt][nt][3]);
                } else {
                    float b0 = bias[c], b1 = bias[c + 1];
                    float v0 = acc[mt][nt][0] + b0, v1 = acc[mt][nt][1] + b1;
                    float v2 = acc[mt][nt][2] + b0, v3 = acc[mt][nt][3] + b1;
                    if constexpr (EPI == EPI_RELU) {
                        v0 = fmaxf(v0, 0.f); v1 = fmaxf(v1, 0.f);
                        v2 = fmaxf(v2, 0.f); v3 = fmaxf(v3, 0.f);
                    }
                    if constexpr (EPI == EPI_ADD) {
                        float2 rl = *(const float2*)&resid[(size_t)r*N + c];
                        float2 rh = *(const float2*)&resid[(size_t)(r+8)*N + c];
                        v0 += rl.x; v1 += rl.y; v2 += rh.x; v3 += rh.y;
                    }
                    *(float2*)&Cg[(size_t)r*N + c]     = make_float2(v0, v1);
                    *(float2*)&Cg[(size_t)(r+8)*N + c] = make_float2(v2, v3);
                }
            }
        }
    }
}

// ---------------- tensor-core attention, 12 warps / forest -------------------
// 384 threads: warp w -> head = w/3, m-tile = w%3 (rows [mt*16, mt*16+16)).
// No redundant tiles; S/softmax/P/O per warp on one 16-row stripe.
#define NP   48
#define QSS  132
#define PSS  52
#define ATTN_SMEM_WORDS (2*NP*QSS + H*PSS)   // 19328
#define ATTN_SMEM_BYTES (ATTN_SMEM_WORDS*4)  // 77312

__global__ __launch_bounds__(384, 2) void attn_k(const float* __restrict__ qkv,
                                                 float* __restrict__ o)
{
    extern __shared__ unsigned sm[];
    unsigned* qs = sm;                 // [48][132]
    unsigned* ks = sm + NP*QSS;        // [48][132]
    unsigned* ps = sm;                 // [4][48][52] overlay (qs/ks dead then)
    unsigned* vt = sm + 2*NP*QSS;      // [128][52]  V^T

    int fb  = blockIdx.x;
    int tid = threadIdx.x;
    size_t base = (size_t)fb * NN * (3*H);

    for (int idx = tid; idx < NP*H; idx += 384) {
        int n = idx >> 7, c = idx & 127;
        unsigned qv = 0, kv = 0, vv = 0;
        if (n < NN) {
            const float* row = &qkv[base + (size_t)n*(3*H)];
            qv = f2tf(row[c]);
            kv = f2tf(row[H + c]);
            vv = f2tf(row[2*H + c]);
        }
        qs[n*QSS + c] = qv;
        ks[n*QSS + c] = kv;
        vt[c*PSS + n] = vv;
    }
    __syncthreads();

    int warp = tid >> 5, lane = tid & 31;
    int gid = lane >> 2, tg = lane & 3;
    int h  = warp / 3;          // 0..3
    int mt = warp - h*3;        // 0..2
    int hc = h * HD;
    int mb = mt * 16;

    // ---- S = Q @ K^T  (one 16-row stripe x 48 cols) ----
    float acc[6][4];
#pragma unroll
    for (int b = 0; b < 6; b++)
#pragma unroll
        for (int c = 0; c < 4; c++) acc[b][c] = 0.f;

#pragma unroll
    for (int k = 0; k < 4; k++) {
        int kk = hc + k*8;
        unsigned af[4], bf[6][2];
        {
            int r = mb + gid;
            af[0] = qs[ r     *QSS + kk + tg];
            af[1] = qs[(r + 8)*QSS + kk + tg];
            af[2] = qs[ r     *QSS + kk + tg + 4];
            af[3] = qs[(r + 8)*QSS + kk + tg + 4];
        }
#pragma unroll
        for (int nt = 0; nt < 6; nt++) {
            int n = nt*8 + gid;
            bf[nt][0] = ks[n*QSS + kk + tg];
            bf[nt][1] = ks[n*QSS + kk + tg + 4];
        }
#pragma unroll
        for (int nt = 0; nt < 6; nt++)
            mma_tf32(acc[nt], af, bf[nt]);
    }
    __syncthreads();   // all reads of qs/ks complete before ps overlay writes

    // ---- softmax (row in this warp's quad; cols >= NN masked) + store P ----
    const float scale = 0.17677669529663687f;   // 1/sqrt(32)
    unsigned* psh = ps + h*(NP*PSS);
    {
        int r0 = mb + gid;
        float m0 = -1e30f, m1 = -1e30f;
#pragma unroll
        for (int nt = 0; nt < 6; nt++) {
            int c0 = nt*8 + 2*tg;
            float v0 = (c0     < NN) ? acc[nt][0]*scale : -1e30f;
            float v1 = (c0 + 1 < NN) ? acc[nt][1]*scale : -1e30f;
            float v2 = (c0     < NN) ? acc[nt][2]*scale : -1e30f;
            float v3 = (c0 + 1 < NN) ? acc[nt][3]*scale : -1e30f;
            acc[nt][0] = v0; acc[nt][1] = v1;
            acc[nt][2] = v2; acc[nt][3] = v3;
            m0 = fmaxf(m0, fmaxf(v0, v1));
            m1 = fmaxf(m1, fmaxf(v2, v3));
        }
        m0 = fmaxf(m0, __shfl_xor_sync(0xffffffffu, m0, 1));
        m0 = fmaxf(m0, __shfl_xor_sync(0xffffffffu, m0, 2));
        m1 = fmaxf(m1, __shfl_xor_sync(0xffffffffu, m1, 1));
        m1 = fmaxf(m1, __shfl_xor_sync(0xffffffffu, m1, 2));
        float s0 = 0.f, s1 = 0.f;
#pragma unroll
        for (int nt = 0; nt < 6; nt++) {
            float p0 = __expf(acc[nt][0] - m0);
            float p1 = __expf(acc[nt][1] - m0);
            float p2 = __expf(acc[nt][2] - m1);
            float p3 = __expf(acc[nt][3] - m1);
            acc[nt][0] = p0; acc[nt][1] = p1;
            acc[nt][2] = p2; acc[nt][3] = p3;
            s0 += p0 + p1; s1 += p2 + p3;
        }
        s0 += __shfl_xor_sync(0xffffffffu, s0, 1);
        s0 += __shfl_xor_sync(0xffffffffu, s0, 2);
        s1 += __shfl_xor_sync(0xffffffffu, s1, 1);
        s1 += __shfl_xor_sync(0xffffffffu, s1, 2);
        float i0 = 1.f / s0, i1 = 1.f / s1;
#pragma unroll
        for (int nt = 0; nt < 6; nt++) {
            int c0 = nt*8 + 2*tg;
            psh[ r0     *PSS + c0    ] = f2tf(acc[nt][0] * i0);
            psh[ r0     *PSS + c0 + 1] = f2tf(acc[nt][1] * i0);
            psh[(r0 + 8)*PSS + c0    ] = f2tf(acc[nt][2] * i1);
            psh[(r0 + 8)*PSS + c0 + 1] = f2tf(acc[nt][3] * i1);
        }
    }
    __syncthreads();

    // ---- O = P @ V  (16 rows x 32 cols) ----
    float oa[4][4];
#pragma unroll
    for (int b = 0; b < 4; b++)
#pragma unroll
        for (int c = 0; c < 4; c++) oa[b][c] = 0.f;

#pragma unroll
    for (int k = 0; k < 6; k++) {
        int kk = k*8;
        unsigned af[4], bf[4][2];
        {
            int r = mb + gid;
            af[0] = psh[ r     *PSS + kk + tg];
            af[1] = psh[(r + 8)*PSS + kk + tg];
            af[2] = psh[ r     *PSS + kk + tg + 4];
            af[3] = psh[(r + 8)*PSS + kk + tg + 4];
        }
#pragma unroll
        for (int nt = 0; nt < 4; nt++) {
            int n = hc + nt*8 + gid;
            bf[nt][0] = vt[n*PSS + kk + tg];
            bf[nt][1] = vt[n*PSS + kk + tg + 4];
        }
#pragma unroll
        for (int nt = 0; nt < 4; nt++)
            mma_tf32(oa[nt], af, bf[nt]);
    }

#pragma unroll
    for (int nt = 0; nt < 4; nt++) {
        int r = mb + gid;
        int c = hc + nt*8 + 2*tg;
        if (r < NN)
            *(float2*)&o[((size_t)(fb*NN + r))*H + c] =
                make_float2(oa[nt][0], oa[nt][1]);
        if (r + 8 < NN)
            *(float2*)&o[((size_t)(fb*NN + r + 8))*H + c] =
                make_float2(oa[nt][2], oa[nt][3]);
    }
}

// ---------------- final LN over OUT=128 ----------------
__global__ __launch_bounds__(128) void lnf_k(const float* __restrict__ fin,
                                             const float* __restrict__ bo,
                                             const float* __restrict__ g,
                                             const float* __restrict__ b,
                                             float* __restrict__ out)
{
    int r = blockIdx.x, c = threadIdx.x;
    float v = fin[(size_t)r*OUTD + c] + bo[c];
    __shared__ float red[4];
    float s = v;
#pragma unroll
    for (int off = 16; off; off >>= 1) s += __shfl_xor_sync(0xffffffffu, s, off);
    if ((c & 31) == 0) red[c >> 5] = s;
    __syncthreads();
    float mu = (red[0] + red[1] + red[2] + red[3]) * (1.f/128.f);
    __syncthreads();
    float d = v - mu;
    float q = d * d;
#pragma unroll
    for (int off = 16; off; off >>= 1) q += __shfl_xor_sync(0xffffffffu, q, off);
    if ((c & 31) == 0) red[c >> 5] = q;
    __syncthreads();
    float var = (red[0] + red[1] + red[2] + red[3]) * (1.f/128.f);
    float rs = rsqrtf(var + 1e-5f);
    out[(size_t)r*OUTD + c] = d * rs * g[c] + b[c];
}

// ---------------- launch ----------------
extern "C" void kernel_launch(void* const* d_in, const int* in_sizes, int n_in,
                              void* d_out, int out_size)
{
    const float* forest = (const float*)d_in[0];
    const int*   adj    = (const int*)  d_in[1];
    const int*   order  = (const int*)  d_in[2];
    const float* W_in   = (const float*)d_in[3];
    const float* b_in   = (const float*)d_in[4];
    const float* qkv_w  = (const float*)d_in[5];
    const float* qkv_b  = (const float*)d_in[6];
    const float* aow    = (const float*)d_in[7];
    const float* aob    = (const float*)d_in[8];
    const float* f1w    = (const float*)d_in[9];
    const float* f1b    = (const float*)d_in[10];
    const float* f2w    = (const float*)d_in[11];
    const float* f2b    = (const float*)d_in[12];
    const float* ln1g   = (const float*)d_in[13];
    const float* ln1b   = (const float*)d_in[14];
    const float* ln2g   = (const float*)d_in[15];
    const float* ln2b   = (const float*)d_in[16];
    const float* Wout   = (const float*)d_in[17];
    const float* bout   = (const float*)d_in[18];
    const float* lnfg   = (const float*)d_in[19];
    const float* lnfb   = (const float*)d_in[20];

    float *px, *ppos, *pqkv, *pfin;
    cudaGetSymbolAddress((void**)&px,   g_x);
    cudaGetSymbolAddress((void**)&ppos, g_pos);
    cudaGetSymbolAddress((void**)&pqkv, g_qkv);
    cudaGetSymbolAddress((void**)&pfin, g_fin);

    cudaFuncSetAttribute(attn_k, cudaFuncAttributeMaxDynamicSharedMemorySize,
                         ATTN_SMEM_BYTES);

    // 1) positional encoding
    pos_kernel<<<FB, 128>>>(adj, order, ppos);

    // 2) embed: x = forest @ W_in^T + b_in + pos
    gemm_tc<EPI_ADD><<<dim3(TT/BM, 1, 1), 256>>>(
        forest, W_in, b_in, ppos, nullptr, nullptr, px, TT, H, NIN);

    for (int l = 0; l < LL; l++) {
        // qkv = x @ qkv_w^T + b    (N = 384)
        gemm_tc<EPI_BIAS><<<dim3(TT/BM, 3, 1), 256>>>(
            px, qkv_w + (size_t)l*3*H*H, qkv_b + (size_t)l*3*H,
            nullptr, nullptr, nullptr, pqkv, TT, 3*H, H);
        // attention -> ppos  (tensor-core, 12 warps)
        attn_k<<<FB, 384, ATTN_SMEM_BYTES>>>(pqkv, ppos);
        // x = LN( attn_out @ aow^T + aob + x )
        gemm_tc<EPI_LN><<<dim3(TT/BM, 1, 1), 256>>>(
            ppos, aow + (size_t)l*H*H, aob + (size_t)l*H, px,
            ln1g + (size_t)l*H, ln1b + (size_t)l*H, px, TT, H, H);
        // hidden = relu(x @ f1w^T + f1b)  (N = 256)
        gemm_tc<EPI_RELU><<<dim3(TT/BM, 2, 1), 256>>>(
            px, f1w + (size_t)l*FF*H, f1b + (size_t)l*FF,
            nullptr, nullptr, nullptr, pqkv, TT, FF, H);
        // x = LN( hidden @ f2w^T + f2b + x )
        gemm_tc<EPI_LN><<<dim3(TT/BM, 1, 1), 256>>>(
            pqkv, f2w + (size_t)l*H*FF, f2b + (size_t)l*H, px,
            ln2g + (size_t)l*H, ln2b + (size_t)l*H, px, TT, H, FF);
    }

    // 3) final: out = LN( x.reshape(FB, NN*H) @ Wout^T + b_out )
    cudaMemsetAsync(pfin, 0, (size_t)FB*OUTD*sizeof(float));
    gemm_tc<EPI_ATOMIC><<<dim3(FB/BM, 1, 8), 256>>>(
        px, Wout, nullptr, nullptr, nullptr, nullptr, pfin, FB, OUTD, NN*H);
    lnf_k<<<FB, 128>>>(pfin, bout, lnfg, lnfb, (float*)d_out);
}

// round 17
// speedup vs baseline: 1.3843x; 1.0629x over previous
#include <cuda_runtime.h>
#include <cuda_fp16.h>
#include <cuda_bf16.h>
#include <math.h>

// ---------------- problem constants ----------------
#define B_    512
#define A_    8
#define NN    42
#define NIN   32
#define H     128
#define BFN   3
#define NH    4
#define LL    2
#define FF    256
#define OUTD  128
#define EE    41
#define HD    32
#define FB    (B_*A_)        // 4096
#define TT    (FB*NN)        // 172032

// ---------------- scratch (no allocs allowed) ----------------
__device__ float g_x[(size_t)TT*H];
__device__ float g_pos[(size_t)TT*H];
__device__ float g_qkv[(size_t)TT*3*H];
__device__ float g_fin[(size_t)FB*OUTD];

// ---------------- positional encoding (single topological pass) ----------------
__global__ __launch_bounds__(128) void pos_kernel(const int* __restrict__ adj,
                                                  const int* __restrict__ order,
                                                  float* __restrict__ pos)
{
    int fb = blockIdx.x;
    int h  = threadIdx.x;
    __shared__ int   par[EE];
    __shared__ int   eidx[EE];
    __shared__ int   dep[NN];
    __shared__ float ps[NN][H];

    if (h < EE) {
        const int* e = &adj[((size_t)fb*EE + h)*3];
        par[h] = e[0] - fb*NN;
        int s = e[2] + 1; s = min(max(s, 0), BFN-1);
        eidx[h] = s;
    }
    __syncthreads();
    if (h == 0) {
        dep[0] = 0;
        for (int e = 0; e < EE; e++) {
            int p  = par[e];
            int dp = dep[p];
            dep[e + 1] = dp + 1;
            eidx[e] = dp * BFN + eidx[e];
        }
    }
    ps[0][h] = 0.f;
    __syncthreads();

#pragma unroll 1
    for (int e = 0; e < EE; e++) {
        float v = ps[par[e]][h] + ((h == eidx[e]) ? 1.f : 0.f);
        ps[e + 1][h] = v;
    }
    for (int n = 0; n < NN; n++)
        pos[((size_t)(fb*NN + n))*H + h] = ps[n][h];
}

// ---------------- helpers ----------------
__device__ __forceinline__ unsigned f2tf(float f)
{
    unsigned u;
    asm("cvt.rna.tf32.f32 %0, %1;" : "=r"(u) : "f"(f));
    return u;
}

__device__ __forceinline__ unsigned f2h2(float a, float b)
{
    __half2 h = __floats2half2_rn(a, b);
    return *(unsigned*)&h;
}

__device__ __forceinline__ void mma_tf32(float* d, const unsigned* a, const unsigned* b)
{
    asm volatile("mma.sync.aligned.m16n8k8.row.col.f32.tf32.tf32.f32 "
                 "{%0,%1,%2,%3}, {%4,%5,%6,%7}, {%8,%9}, {%0,%1,%2,%3};\n"
                 : "+f"(d[0]), "+f"(d[1]), "+f"(d[2]), "+f"(d[3])
                 : "r"(a[0]), "r"(a[1]), "r"(a[2]), "r"(a[3]),
                   "r"(b[0]), "r"(b[1]));
}

__device__ __forceinline__ void mma_f16(float* d, const unsigned* a, const unsigned* b)
{
    asm volatile("mma.sync.aligned.m16n8k16.row.col.f32.f16.f16.f32 "
                 "{%0,%1,%2,%3}, {%4,%5,%6,%7}, {%8,%9}, {%0,%1,%2,%3};\n"
                 : "+f"(d[0]), "+f"(d[1]), "+f"(d[2]), "+f"(d[3])
                 : "r"(a[0]), "r"(a[1]), "r"(a[2]), "r"(a[3]),
                   "r"(b[0]), "r"(b[1]));
}

// ---------------- FP16 tensor-core GEMM  C = A[M,K] @ W[N,K]^T ---------------
// Double-buffered smem, register prefetch, fp32->fp16 convert at STS,
// fp32 accumulation. Row stride 12 words (24 halfs): conflict-free frag LDS.
#define BM   128
#define BN   128
#define BK   16
#define LDKW 12      // words (half2) per row

#define EPI_BIAS   0
#define EPI_RELU   1
#define EPI_ADD    2
#define EPI_ATOMIC 3
#define EPI_LN     4

template<int EPI>
__global__ __launch_bounds__(256)
void gemm_tc(const float* __restrict__ Ag, const float* __restrict__ Wg,
             const float* __restrict__ bias, const float* __restrict__ resid,
             const float* __restrict__ gam,  const float* __restrict__ bet,
             float* __restrict__ Cg, int M, int N, int K)
{
    __shared__ unsigned As[2][BM*LDKW];   // 12KB
    __shared__ unsigned Bs[2][BN*LDKW];   // 12KB

    int m0 = blockIdx.x * BM;
    int n0 = blockIdx.y * BN;
    int per = K / gridDim.z;
    int ks  = blockIdx.z * per;
    int ke  = ks + per;

    int tid  = threadIdx.x;
    int lane = tid & 31;
    int warp = tid >> 5;
    int wm = warp >> 2;
    int wn = warp & 3;
    int gid = lane >> 2;
    int tg  = lane & 3;
    int lrow = tid >> 1;
    int lcol = (tid & 1) * 8;          // float offset in K
    int sw   = lrow*LDKW + (tid & 1)*4; // smem word offset for this thread's 8 halfs

    float acc[4][4][4];
#pragma unroll
    for (int i = 0; i < 4; i++)
#pragma unroll
        for (int j = 0; j < 4; j++)
#pragma unroll
            for (int k = 0; k < 4; k++) acc[i][j][k] = 0.f;

    const float* Ap = Ag + (size_t)(m0 + lrow) * K + lcol;
    const float* Wp = Wg + (size_t)(n0 + lrow) * K + lcol;

    float4 av0, av1, wv0, wv1;

    av0 = *(const float4*)(Ap + ks);
    av1 = *(const float4*)(Ap + ks + 4);
    wv0 = *(const float4*)(Wp + ks);
    wv1 = *(const float4*)(Wp + ks + 4);
    *(uint4*)&As[0][sw] = make_uint4(f2h2(av0.x, av0.y), f2h2(av0.z, av0.w),
                                     f2h2(av1.x, av1.y), f2h2(av1.z, av1.w));
    *(uint4*)&Bs[0][sw] = make_uint4(f2h2(wv0.x, wv0.y), f2h2(wv0.z, wv0.w),
                                     f2h2(wv1.x, wv1.y), f2h2(wv1.z, wv1.w));
    __syncthreads();

    int cur = 0;
    for (int kt = ks; kt < ke; kt += BK) {
        bool more = (kt + BK) < ke;
        if (more) {
            av0 = *(const float4*)(Ap + kt + BK);
            av1 = *(const float4*)(Ap + kt + BK + 4);
            wv0 = *(const float4*)(Wp + kt + BK);
            wv1 = *(const float4*)(Wp + kt + BK + 4);
        }

        {
            const unsigned* Ac = As[cur];
            const unsigned* Bc = Bs[cur];
            unsigned af[4][4], bf[4][2];
#pragma unroll
            for (int mt = 0; mt < 4; mt++) {
                int r = wm*64 + mt*16 + gid;
                af[mt][0] = Ac[ r     *LDKW + tg];
                af[mt][1] = Ac[(r + 8)*LDKW + tg];
                af[mt][2] = Ac[ r     *LDKW + 4 + tg];
                af[mt][3] = Ac[(r + 8)*LDKW + 4 + tg];
            }
#pragma unroll
            for (int nt = 0; nt < 4; nt++) {
                int c = wn*32 + nt*8 + gid;
                bf[nt][0] = Bc[c*LDKW + tg];
                bf[nt][1] = Bc[c*LDKW + 4 + tg];
            }
#pragma unroll
            for (int mt = 0; mt < 4; mt++)
#pragma unroll
                for (int nt = 0; nt < 4; nt++)
                    mma_f16(acc[mt][nt], af[mt], bf[nt]);
        }

        if (more) {
            int nxt = cur ^ 1;
            *(uint4*)&As[nxt][sw] = make_uint4(f2h2(av0.x, av0.y), f2h2(av0.z, av0.w),
                                               f2h2(av1.x, av1.y), f2h2(av1.z, av1.w));
            *(uint4*)&Bs[nxt][sw] = make_uint4(f2h2(wv0.x, wv0.y), f2h2(wv0.z, wv0.w),
                                               f2h2(wv1.x, wv1.y), f2h2(wv1.z, wv1.w));
            __syncthreads();
        }
        cur ^= 1;
    }

    if constexpr (EPI == EPI_LN) {
        __shared__ float red1[BM][4];
        __shared__ float red2[BM][4];
        float mu0[4], mu1[4];

#pragma unroll
        for (int mt = 0; mt < 4; mt++) {
            int r = m0 + wm*64 + mt*16 + gid;
            float s0 = 0.f, s1 = 0.f;
#pragma unroll
            for (int nt = 0; nt < 4; nt++) {
                int c = wn*32 + nt*8 + 2*tg;
                float b0 = bias[c], b1 = bias[c + 1];
                float2 rl = *(const float2*)&resid[(size_t)r*128 + c];
                float2 rh = *(const float2*)&resid[(size_t)(r+8)*128 + c];
                acc[mt][nt][0] += b0 + rl.x;
                acc[mt][nt][1] += b1 + rl.y;
                acc[mt][nt][2] += b0 + rh.x;
                acc[mt][nt][3] += b1 + rh.y;
                s0 += acc[mt][nt][0] + acc[mt][nt][1];
                s1 += acc[mt][nt][2] + acc[mt][nt][3];
            }
            s0 += __shfl_xor_sync(0xffffffffu, s0, 1);
            s0 += __shfl_xor_sync(0xffffffffu, s0, 2);
            s1 += __shfl_xor_sync(0xffffffffu, s1, 1);
            s1 += __shfl_xor_sync(0xffffffffu, s1, 2);
            if (tg == 0) {
                red1[wm*64 + mt*16 + gid    ][wn] = s0;
                red1[wm*64 + mt*16 + gid + 8][wn] = s1;
            }
        }
        __syncthreads();
#pragma unroll
        for (int mt = 0; mt < 4; mt++) {
            int rl_ = wm*64 + mt*16 + gid;
            mu0[mt] = (red1[rl_    ][0] + red1[rl_    ][1] + red1[rl_    ][2] + red1[rl_    ][3]) * (1.f/128.f);
            mu1[mt] = (red1[rl_ + 8][0] + red1[rl_ + 8][1] + red1[rl_ + 8][2] + red1[rl_ + 8][3]) * (1.f/128.f);
            float q0 = 0.f, q1 = 0.f;
#pragma unroll
            for (int nt = 0; nt < 4; nt++) {
                float d0 = acc[mt][nt][0] - mu0[mt];
                float d1 = acc[mt][nt][1] - mu0[mt];
                float d2 = acc[mt][nt][2] - mu1[mt];
                float d3 = acc[mt][nt][3] - mu1[mt];
                q0 += d0*d0 + d1*d1;
                q1 += d2*d2 + d3*d3;
            }
            q0 += __shfl_xor_sync(0xffffffffu, q0, 1);
            q0 += __shfl_xor_sync(0xffffffffu, q0, 2);
            q1 += __shfl_xor_sync(0xffffffffu, q1, 1);
            q1 += __shfl_xor_sync(0xffffffffu, q1, 2);
            if (tg == 0) {
                red2[rl_    ][wn] = q0;
                red2[rl_ + 8][wn] = q1;
            }
        }
        __syncthreads();
#pragma unroll
        for (int mt = 0; mt < 4; mt++) {
            int rl_ = wm*64 + mt*16 + gid;
            int r = m0 + rl_;
            float rs0 = rsqrtf((red2[rl_    ][0] + red2[rl_    ][1] + red2[rl_    ][2] + red2[rl_    ][3]) * (1.f/128.f) + 1e-5f);
            float rs1 = rsqrtf((red2[rl_ + 8][0] + red2[rl_ + 8][1] + red2[rl_ + 8][2] + red2[rl_ + 8][3]) * (1.f/128.f) + 1e-5f);
#pragma unroll
            for (int nt = 0; nt < 4; nt++) {
                int c = wn*32 + nt*8 + 2*tg;
                float g0 = gam[c], g1 = gam[c + 1];
                float e0 = bet[c], e1 = bet[c + 1];
                float v0 = (acc[mt][nt][0] - mu0[mt]) * rs0 * g0 + e0;
                float v1 = (acc[mt][nt][1] - mu0[mt]) * rs0 * g1 + e1;
                float v2 = (acc[mt][nt][2] - mu1[mt]) * rs1 * g0 + e0;
                float v3 = (acc[mt][nt][3] - mu1[mt]) * rs1 * g1 + e1;
                *(float2*)&Cg[(size_t)r*128 + c]     = make_float2(v0, v1);
                *(float2*)&Cg[(size_t)(r+8)*128 + c] = make_float2(v2, v3);
            }
        }
    } else {
#pragma unroll
        for (int mt = 0; mt < 4; mt++) {
#pragma unroll
            for (int nt = 0; nt < 4; nt++) {
                int r = m0 + wm*64 + mt*16 + gid;
                int c = n0 + wn*32 + nt*8 + 2*tg;
                if constexpr (EPI == EPI_ATOMIC) {
                    atomicAdd(&Cg[(size_t)r*N + c],         acc[mt][nt][0]);
                    atomicAdd(&Cg[(size_t)r*N + c + 1],     acc[mt][nt][1]);
                    atomicAdd(&Cg[(size_t)(r+8)*N + c],     acc[mt][nt][2]);
                    atomicAdd(&Cg[(size_t)(r+8)*N + c + 1], acc[mt][nt][3]);
                } else {
                    float b0 = bias[c], b1 = bias[c + 1];
                    float v0 = acc[mt][nt][0] + b0, v1 = acc[mt][nt][1] + b1;
                    float v2 = acc[mt][nt][2] + b0, v3 = acc[mt][nt][3] + b1;
                    if constexpr (EPI == EPI_RELU) {
                        v0 = fmaxf(v0, 0.f); v1 = fmaxf(v1, 0.f);
                        v2 = fmaxf(v2, 0.f); v3 = fmaxf(v3, 0.f);
                    }
                    if constexpr (EPI == EPI_ADD) {
                        float2 rl = *(const float2*)&resid[(size_t)r*N + c];
                        float2 rh = *(const float2*)&resid[(size_t)(r+8)*N + c];
                        v0 += rl.x; v1 += rl.y; v2 += rh.x; v3 += rh.y;
                    }
                    *(float2*)&Cg[(size_t)r*N + c]     = make_float2(v0, v1);
                    *(float2*)&Cg[(size_t)(r+8)*N + c] = make_float2(v2, v3);
                }
            }
        }
    }
}

// ---------------- tensor-core attention, 12 warps / forest -------------------
// 384 threads: warp w -> head = w/3, m-tile = w%3. (unchanged from R16)
#define NP   48
#define QSS  132
#define PSS  52
#define ATTN_SMEM_WORDS (2*NP*QSS + H*PSS)   // 19328
#define ATTN_SMEM_BYTES (ATTN_SMEM_WORDS*4)  // 77312

__global__ __launch_bounds__(384, 2) void attn_k(const float* __restrict__ qkv,
                                                 float* __restrict__ o)
{
    extern __shared__ unsigned sm[];
    unsigned* qs = sm;                 // [48][132]
    unsigned* ks = sm + NP*QSS;        // [48][132]
    unsigned* ps = sm;                 // [4][48][52] overlay (qs/ks dead then)
    unsigned* vt = sm + 2*NP*QSS;      // [128][52]  V^T

    int fb  = blockIdx.x;
    int tid = threadIdx.x;
    size_t base = (size_t)fb * NN * (3*H);

    for (int idx = tid; idx < NP*H; idx += 384) {
        int n = idx >> 7, c = idx & 127;
        unsigned qv = 0, kv = 0, vv = 0;
        if (n < NN) {
            const float* row = &qkv[base + (size_t)n*(3*H)];
            qv = f2tf(row[c]);
            kv = f2tf(row[H + c]);
            vv = f2tf(row[2*H + c]);
        }
        qs[n*QSS + c] = qv;
        ks[n*QSS + c] = kv;
        vt[c*PSS + n] = vv;
    }
    __syncthreads();

    int warp = tid >> 5, lane = tid & 31;
    int gid = lane >> 2, tg = lane & 3;
    int h  = warp / 3;
    int mt = warp - h*3;
    int hc = h * HD;
    int mb = mt * 16;

    // ---- S = Q @ K^T ----
    float acc[6][4];
#pragma unroll
    for (int b = 0; b < 6; b++)
#pragma unroll
        for (int c = 0; c < 4; c++) acc[b][c] = 0.f;

#pragma unroll
    for (int k = 0; k < 4; k++) {
        int kk = hc + k*8;
        unsigned af[4], bf[6][2];
        {
            int r = mb + gid;
            af[0] = qs[ r     *QSS + kk + tg];
            af[1] = qs[(r + 8)*QSS + kk + tg];
            af[2] = qs[ r     *QSS + kk + tg + 4];
            af[3] = qs[(r + 8)*QSS + kk + tg + 4];
        }
#pragma unroll
        for (int nt = 0; nt < 6; nt++) {
            int n = nt*8 + gid;
            bf[nt][0] = ks[n*QSS + kk + tg];
            bf[nt][1] = ks[n*QSS + kk + tg + 4];
        }
#pragma unroll
        for (int nt = 0; nt < 6; nt++)
            mma_tf32(acc[nt], af, bf[nt]);
    }
    __syncthreads();

    // ---- softmax + store P (tf32) ----
    const float scale = 0.17677669529663687f;   // 1/sqrt(32)
    unsigned* psh = ps + h*(NP*PSS);
    {
        int r0 = mb + gid;
        float m0 = -1e30f, m1 = -1e30f;
#pragma unroll
        for (int nt = 0; nt < 6; nt++) {
            int c0 = nt*8 + 2*tg;
            float v0 = (c0     < NN) ? acc[nt][0]*scale : -1e30f;
            float v1 = (c0 + 1 < NN) ? acc[nt][1]*scale : -1e30f;
            float v2 = (c0     < NN) ? acc[nt][2]*scale : -1e30f;
            float v3 = (c0 + 1 < NN) ? acc[nt][3]*scale : -1e30f;
            acc[nt][0] = v0; acc[nt][1] = v1;
            acc[nt][2] = v2; acc[nt][3] = v3;
            m0 = fmaxf(m0, fmaxf(v0, v1));
            m1 = fmaxf(m1, fmaxf(v2, v3));
        }
        m0 = fmaxf(m0, __shfl_xor_sync(0xffffffffu, m0, 1));
        m0 = fmaxf(m0, __shfl_xor_sync(0xffffffffu, m0, 2));
        m1 = fmaxf(m1, __shfl_xor_sync(0xffffffffu, m1, 1));
        m1 = fmaxf(m1, __shfl_xor_sync(0xffffffffu, m1, 2));
        float s0 = 0.f, s1 = 0.f;
#pragma unroll
        for (int nt = 0; nt < 6; nt++) {
            float p0 = __expf(acc[nt][0] - m0);
            float p1 = __expf(acc[nt][1] - m0);
            float p2 = __expf(acc[nt][2] - m1);
            float p3 = __expf(acc[nt][3] - m1);
            acc[nt][0] = p0; acc[nt][1] = p1;
            acc[nt][2] = p2; acc[nt][3] = p3;
            s0 += p0 + p1; s1 += p2 + p3;
        }
        s0 += __shfl_xor_sync(0xffffffffu, s0, 1);
        s0 += __shfl_xor_sync(0xffffffffu, s0, 2);
        s1 += __shfl_xor_sync(0xffffffffu, s1, 1);
        s1 += __shfl_xor_sync(0xffffffffu, s1, 2);
        float i0 = 1.f / s0, i1 = 1.f / s1;
#pragma unroll
        for (int nt = 0; nt < 6; nt++) {
            int c0 = nt*8 + 2*tg;
            psh[ r0     *PSS + c0    ] = f2tf(acc[nt][0] * i0);
            psh[ r0     *PSS + c0 + 1] = f2tf(acc[nt][1] * i0);
            psh[(r0 + 8)*PSS + c0    ] = f2tf(acc[nt][2] * i1);
            psh[(r0 + 8)*PSS + c0 + 1] = f2tf(acc[nt][3] * i1);
        }
    }
    __syncthreads();

    // ---- O = P @ V ----
    float oa[4][4];
#pragma unroll
    for (int b = 0; b < 4; b++)
#pragma unroll
        for (int c = 0; c < 4; c++) oa[b][c] = 0.f;

#pragma unroll
    for (int k = 0; k < 6; k++) {
        int kk = k*8;
        unsigned af[4], bf[4][2];
        {
            int r = mb + gid;
            af[0] = psh[ r     *PSS + kk + tg];
            af[1] = psh[(r + 8)*PSS + kk + tg];
            af[2] = psh[ r     *PSS + kk + tg + 4];
            af[3] = psh[(r + 8)*PSS + kk + tg + 4];
        }
#pragma unroll
        for (int nt = 0; nt < 4; nt++) {
            int n = hc + nt*8 + gid;
            bf[nt][0] = vt[n*PSS + kk + tg];
            bf[nt][1] = vt[n*PSS + kk + tg + 4];
        }
#pragma unroll
        for (int nt = 0; nt < 4; nt++)
            mma_tf32(oa[nt], af, bf[nt]);
    }

#pragma unroll
    for (int nt = 0; nt < 4; nt++) {
        int r = mb + gid;
        int c = hc + nt*8 + 2*tg;
        if (r < NN)
            *(float2*)&o[((size_t)(fb*NN + r))*H + c] =
                make_float2(oa[nt][0], oa[nt][1]);
        if (r + 8 < NN)
            *(float2*)&o[((size_t)(fb*NN + r + 8))*H + c] =
                make_float2(oa[nt][2], oa[nt][3]);
    }
}

// ---------------- final LN over OUT=128 ----------------
__global__ __launch_bounds__(128) void lnf_k(const float* __restrict__ fin,
                                             const float* __restrict__ bo,
                                             const float* __restrict__ g,
                                             const float* __restrict__ b,
                                             float* __restrict__ out)
{
    int r = blockIdx.x, c = threadIdx.x;
    float v = fin[(size_t)r*OUTD + c] + bo[c];
    __shared__ float red[4];
    float s = v;
#pragma unroll
    for (int off = 16; off; off >>= 1) s += __shfl_xor_sync(0xffffffffu, s, off);
    if ((c & 31) == 0) red[c >> 5] = s;
    __syncthreads();
    float mu = (red[0] + red[1] + red[2] + red[3]) * (1.f/128.f);
    __syncthreads();
    float d = v - mu;
    float q = d * d;
#pragma unroll
    for (int off = 16; off; off >>= 1) q += __shfl_xor_sync(0xffffffffu, q, off);
    if ((c & 31) == 0) red[c >> 5] = q;
    __syncthreads();
    float var = (red[0] + red[1] + red[2] + red[3]) * (1.f/128.f);
    float rs = rsqrtf(var + 1e-5f);
    out[(size_t)r*OUTD + c] = d * rs * g[c] + b[c];
}

// ---------------- launch ----------------
extern "C" void kernel_launch(void* const* d_in, const int* in_sizes, int n_in,
                              void* d_out, int out_size)
{
    const float* forest = (const float*)d_in[0];
    const int*   adj    = (const int*)  d_in[1];
    const int*   order  = (const int*)  d_in[2];
    const float* W_in   = (const float*)d_in[3];
    const float* b_in   = (const float*)d_in[4];
    const float* qkv_w  = (const float*)d_in[5];
    const float* qkv_b  = (const float*)d_in[6];
    const float* aow    = (const float*)d_in[7];
    const float* aob    = (const float*)d_in[8];
    const float* f1w    = (const float*)d_in[9];
    const float* f1b    = (const float*)d_in[10];
    const float* f2w    = (const float*)d_in[11];
    const float* f2b    = (const float*)d_in[12];
    const float* ln1g   = (const float*)d_in[13];
    const float* ln1b   = (const float*)d_in[14];
    const float* ln2g   = (const float*)d_in[15];
    const float* ln2b   = (const float*)d_in[16];
    const float* Wout   = (const float*)d_in[17];
    const float* bout   = (const float*)d_in[18];
    const float* lnfg   = (const float*)d_in[19];
    const float* lnfb   = (const float*)d_in[20];

    float *px, *ppos, *pqkv, *pfin;
    cudaGetSymbolAddress((void**)&px,   g_x);
    cudaGetSymbolAddress((void**)&ppos, g_pos);
    cudaGetSymbolAddress((void**)&pqkv, g_qkv);
    cudaGetSymbolAddress((void**)&pfin, g_fin);

    cudaFuncSetAttribute(attn_k, cudaFuncAttributeMaxDynamicSharedMemorySize,
                         ATTN_SMEM_BYTES);

    // 1) positional encoding
    pos_kernel<<<FB, 128>>>(adj, order, ppos);

    // 2) embed: x = forest @ W_in^T + b_in + pos
    gemm_tc<EPI_ADD><<<dim3(TT/BM, 1, 1), 256>>>(
        forest, W_in, b_in, ppos, nullptr, nullptr, px, TT, H, NIN);

    for (int l = 0; l < LL; l++) {
        // qkv = x @ qkv_w^T + b    (N = 384)
        gemm_tc<EPI_BIAS><<<dim3(TT/BM, 3, 1), 256>>>(
            px, qkv_w + (size_t)l*3*H*H, qkv_b + (size_t)l*3*H,
            nullptr, nullptr, nullptr, pqkv, TT, 3*H, H);
        // attention -> ppos  (tensor-core, 12 warps)
        attn_k<<<FB, 384, ATTN_SMEM_BYTES>>>(pqkv, ppos);
        // x = LN( attn_out @ aow^T + aob + x )
        gemm_tc<EPI_LN><<<dim3(TT/BM, 1, 1), 256>>>(
            ppos, aow + (size_t)l*H*H, aob + (size_t)l*H, px,
            ln1g + (size_t)l*H, ln1b + (size_t)l*H, px, TT, H, H);
        // hidden = relu(x @ f1w^T + f1b)  (N = 256)
        gemm_tc<EPI_RELU><<<dim3(TT/BM, 2, 1), 256>>>(
            px, f1w + (size_t)l*FF*H, f1b + (size_t)l*FF,
            nullptr, nullptr, nullptr, pqkv, TT, FF, H);
        // x = LN( hidden @ f2w^T + f2b + x )
        gemm_tc<EPI_LN><<<dim3(TT/BM, 1, 1), 256>>>(
            pqkv, f2w + (size_t)l*H*FF, f2b + (size_t)l*H, px,
            ln2g + (size_t)l*H, ln2b + (size_t)l*H, px, TT, H, FF);
    }

    // 3) final: out = LN( x.reshape(FB, NN*H) @ Wout^T + b_out )
    cudaMemsetAsync(pfin, 0, (size_t)FB*OUTD*sizeof(float));
    gemm_tc<EPI_ATOMIC><<<dim3(FB/BM, 1, 8), 256>>>(
        px, Wout, nullptr, nullptr, nullptr, nullptr, pfin, FB, OUTD, NN*H);
    lnf_k<<<FB, 128>>>(pfin, bout, lnfg, lnfb, (float*)d_out);
}